// round 3
// baseline (speedup 1.0000x reference)
#include <cuda_runtime.h>
#include <cuda_bf16.h>
#include <cstdint>

// LogicLayer: y[n, j] = c0[j] + c1[j]*a + c2[j]*b + c3[j]*a*b
//   (c0..c3) = softmax(weights[j,:16]) @ GATE_COEFS
//   a = x[n, idx_a[j]], b = x[n, idx_b[j]]    (idx arrays int32 or int64, detected)
// x: [16384,4096] f32 -> y: [16384,4096] f32

#define IN_DIM   4096
#define OUT_DIM  4096
#define BATCH    16384
#define ROWS     4
#define THREADS  512
#define NWARPS   (THREADS / 32)                 // 16
#define NITER    (OUT_DIM / (THREADS * 4))      // 2
#define NWIN     (NITER * NWARPS)               // 32 windows of 128 j's

__device__ float4   g_coef[OUT_DIM];            // natural order (intermediate)
__device__ int2     g_idx [OUT_DIM];
__device__ float4   g_coefp[NWIN * 4 * 32];     // [(win*4+k)*32 + lane]
__device__ unsigned g_meta [NWIN * 4 * 32];     // a(12) | b(12)<<12 | q(5)<<24

__constant__ float G0[16] = {0,0,0,0, 0,0,0,0, 1,1,1,1, 1,1,1,1};
__constant__ float G1[16] = {0,0,1,1, 0,0,1,1, -1,-1,0,0, -1,-1,0,0};
__constant__ float G2[16] = {0,0,0,0, 1,1,1,1, -1,-1,-1,-1, 0,0,0,0};
__constant__ float G3[16] = {0,1,-1,0, -1,0,-2,-1, 1,2,0,1, 0,1,-1,0};

__device__ __forceinline__ bool idx_is_i64(const int* p)
{
    bool i64 = true;
    #pragma unroll
    for (int i = 0; i < 16; ++i) {
        int lo = p[2 * i], hi = p[2 * i + 1];
        if (hi != 0 || (unsigned)lo >= IN_DIM) { i64 = false; break; }
    }
    return i64;
}
__device__ __forceinline__ int load_idx(const int* p, bool i64, int j)
{
    int v = i64 ? p[2 * j] : p[j];
    return (v < 0) ? 0 : (v >= IN_DIM ? IN_DIM - 1 : v);
}

__global__ void precompute_kernel(const float* __restrict__ w,
                                  const int* __restrict__ ia,
                                  const int* __restrict__ ib)
{
    int j = blockIdx.x * blockDim.x + threadIdx.x;
    if (j >= OUT_DIM) return;
    const bool a64 = idx_is_i64(ia);
    const bool b64 = idx_is_i64(ib);

    const float* wr = w + j * 16;
    float wv[16]; float m = -1e30f;
    #pragma unroll
    for (int i = 0; i < 16; ++i) { wv[i] = wr[i]; m = fmaxf(m, wv[i]); }
    float s = 0.f;
    #pragma unroll
    for (int i = 0; i < 16; ++i) { wv[i] = expf(wv[i] - m); s += wv[i]; }
    float inv = 1.0f / s;
    float c0 = 0.f, c1 = 0.f, c2 = 0.f, c3 = 0.f;
    #pragma unroll
    for (int i = 0; i < 16; ++i) {
        float p = wv[i] * inv;
        c0 = fmaf(p, G0[i], c0); c1 = fmaf(p, G1[i], c1);
        c2 = fmaf(p, G2[i], c2); c3 = fmaf(p, G3[i], c3);
    }
    g_coef[j] = make_float4(c0, c1, c2, c3);
    g_idx[j]  = make_int2(load_idx(ia, a64, j), load_idx(ib, b64, j));
}

// Build permuted, coalesced tables. One thread per window (128 consecutive j's
// = 32 quads). Greedy: assign quads to the 4 eight-lane LDS phases minimizing
// shared-memory bank-group (c&7) collisions for a and b across all 4 k's.
__global__ void build_tables_kernel()
{
    int win = threadIdx.x;
    if (win >= NWIN) return;
    const int iter = win / NWARPS, w = win % NWARPS;
    const int jbase = iter * (THREADS * 4) + w * 128;

    unsigned char cntA[4][4][8] = {};  // [phase][k][group]
    unsigned char cntB[4][4][8] = {};
    unsigned char fill[4] = {};
    unsigned char sigma[32];           // lane -> quad

    for (int q = 0; q < 32; ++q) {
        int ga[4], gb[4];
        #pragma unroll
        for (int k = 0; k < 4; ++k) {
            int2 ij = g_idx[jbase + q * 4 + k];
            ga[k] = ij.x & 7; gb[k] = ij.y & 7;
        }
        int bestp = -1, bestc = 1 << 30;
        for (int p = 0; p < 4; ++p) {
            if (fill[p] >= 8) continue;
            int c = 0;
            #pragma unroll
            for (int k = 0; k < 4; ++k)
                c += cntA[p][k][ga[k]] + cntB[p][k][gb[k]];
            if (c < bestc) { bestc = c; bestp = p; }
        }
        #pragma unroll
        for (int k = 0; k < 4; ++k) { cntA[bestp][k][ga[k]]++; cntB[bestp][k][gb[k]]++; }
        sigma[bestp * 8 + fill[bestp]] = (unsigned char)q;
        fill[bestp]++;
    }

    for (int l = 0; l < 32; ++l) {
        int q = sigma[l];
        #pragma unroll
        for (int k = 0; k < 4; ++k) {
            int j = jbase + q * 4 + k;
            int2 ij = g_idx[j];
            g_coefp[(win * 4 + k) * 32 + l] = g_coef[j];
            g_meta [(win * 4 + k) * 32 + l] =
                (unsigned)ij.x | ((unsigned)ij.y << 12) | ((unsigned)q << 24);
        }
    }
}

// Main kernel: each block does ROWS=4 rows x all 4096 outputs.
// smem: x tile transposed as float4 per column: xs4[c] = {row0..row3}.
__global__ __launch_bounds__(THREADS, 2)
void logic_main_kernel(const float* __restrict__ x, float* __restrict__ y)
{
    extern __shared__ float xs[];   // IN_DIM * ROWS floats (64 KB)

    const int row0 = blockIdx.x * ROWS;
    const int t    = threadIdx.x;
    const int lane = t & 31;
    const int w    = t >> 5;

    // stage 4 rows transposed (lane: row = l&3, colgroup = l>>2)
    {
        const int r  = lane & 3;
        const int cg = lane >> 2;
        const float* xrow = x + (size_t)(row0 + r) * IN_DIM;
        const int cbeg = w * (IN_DIM / NWARPS);        // 256 cols per warp
        #pragma unroll 4
        for (int base = cbeg; base < cbeg + (IN_DIM / NWARPS); base += 8) {
            int c = base + cg;
            xs[c * ROWS + r] = __ldg(xrow + c);
        }
    }
    __syncthreads();

    const float4* __restrict__ xs4 = (const float4*)xs;

    #pragma unroll
    for (int iter = 0; iter < NITER; ++iter) {
        const int win   = iter * NWARPS + w;
        const int jbase = iter * (THREADS * 4) + w * 128;
        const int tbase = (win * 4) * 32 + lane;

        float4   cf[4];
        unsigned mt[4];
        #pragma unroll
        for (int k = 0; k < 4; ++k) {
            cf[k] = g_coefp[tbase + k * 32];
            mt[k] = g_meta [tbase + k * 32];
        }

        float out[ROWS][4];
        #pragma unroll
        for (int k = 0; k < 4; ++k) {
            const float4 a = xs4[mt[k] & 0xFFFu];
            const float4 b = xs4[(mt[k] >> 12) & 0xFFFu];
            const float c0 = cf[k].x, c1 = cf[k].y, c2 = cf[k].z, c3 = cf[k].w;
            out[0][k] = fmaf(b.x, fmaf(c3, a.x, c2), fmaf(c1, a.x, c0));
            out[1][k] = fmaf(b.y, fmaf(c3, a.y, c2), fmaf(c1, a.y, c0));
            out[2][k] = fmaf(b.z, fmaf(c3, a.z, c2), fmaf(c1, a.z, c0));
            out[3][k] = fmaf(b.w, fmaf(c3, a.w, c2), fmaf(c1, a.w, c0));
        }

        const int col = jbase + (int)(mt[0] >> 24) * 4;   // this thread's quad
        #pragma unroll
        for (int r = 0; r < ROWS; ++r) {
            float4 v = make_float4(out[r][0], out[r][1], out[r][2], out[r][3]);
            *(float4*)(y + (size_t)(row0 + r) * OUT_DIM + col) = v;
        }
    }
}

extern "C" void kernel_launch(void* const* d_in, const int* in_sizes, int n_in,
                              void* d_out, int out_size)
{
    const float* x  = (const float*)d_in[0];
    const float* wt = (const float*)d_in[1];
    const int*   ia = (const int*)d_in[2];
    const int*   ib = (const int*)d_in[3];
    float*       y  = (float*)d_out;

    cudaFuncSetAttribute(logic_main_kernel,
                         cudaFuncAttributeMaxDynamicSharedMemorySize,
                         IN_DIM * ROWS * (int)sizeof(float));

    precompute_kernel<<<(OUT_DIM + 255) / 256, 256>>>(wt, ia, ib);
    build_tables_kernel<<<1, NWIN>>>();

    const int smem = IN_DIM * ROWS * (int)sizeof(float);
    logic_main_kernel<<<BATCH / ROWS, THREADS, smem>>>(x, y);
}

// round 4
// speedup vs baseline: 2.0964x; 2.0964x over previous
#include <cuda_runtime.h>
#include <cuda_bf16.h>
#include <cstdint>

// LogicLayer: y[n, j] = c0[j] + c1[j]*a + c2[j]*b + c3[j]*a*b
//   (c0..c3) = softmax(weights[j,:16]) @ GATE_COEFS
//   a = x[n, idx_a[j]], b = x[n, idx_b[j]]   (idx int32 or int64, detected)
// x: [16384,4096] f32 -> y: [16384,4096] f32

#define IN_DIM   4096
#define OUT_DIM  4096
#define BATCH    16384
#define ROWS     4
#define THREADS  512
#define NWARPS   (THREADS / 32)             // 16
#define NITER    (OUT_DIM / (4 * THREADS))  // 2

__device__ float4 g_coef[OUT_DIM];
__device__ int2   g_idx [OUT_DIM];

__constant__ float G0[16] = {0,0,0,0, 0,0,0,0, 1,1,1,1, 1,1,1,1};
__constant__ float G1[16] = {0,0,1,1, 0,0,1,1, -1,-1,0,0, -1,-1,0,0};
__constant__ float G2[16] = {0,0,0,0, 1,1,1,1, -1,-1,-1,-1, 0,0,0,0};
__constant__ float G3[16] = {0,1,-1,0, -1,0,-2,-1, 1,2,0,1, 0,1,-1,0};

__device__ __forceinline__ bool idx_is_i64(const int* p)
{
    bool i64 = true;
    #pragma unroll
    for (int i = 0; i < 16; ++i) {
        int lo = p[2 * i], hi = p[2 * i + 1];
        if (hi != 0 || (unsigned)lo >= IN_DIM) { i64 = false; break; }
    }
    return i64;
}
__device__ __forceinline__ int load_idx(const int* p, bool i64, int j)
{
    int v = i64 ? p[2 * j] : p[j];
    return (v < 0) ? 0 : (v >= IN_DIM ? IN_DIM - 1 : v);
}

__global__ void precompute_kernel(const float* __restrict__ w,
                                  const int* __restrict__ ia,
                                  const int* __restrict__ ib)
{
    int j = blockIdx.x * blockDim.x + threadIdx.x;
    if (j >= OUT_DIM) return;
    const bool a64 = idx_is_i64(ia);
    const bool b64 = idx_is_i64(ib);

    const float* wr = w + j * 16;
    float wv[16]; float m = -1e30f;
    #pragma unroll
    for (int i = 0; i < 16; ++i) { wv[i] = wr[i]; m = fmaxf(m, wv[i]); }
    float s = 0.f;
    #pragma unroll
    for (int i = 0; i < 16; ++i) { wv[i] = expf(wv[i] - m); s += wv[i]; }
    float inv = 1.0f / s;
    float c0 = 0.f, c1 = 0.f, c2 = 0.f, c3 = 0.f;
    #pragma unroll
    for (int i = 0; i < 16; ++i) {
        float p = wv[i] * inv;
        c0 = fmaf(p, G0[i], c0); c1 = fmaf(p, G1[i], c1);
        c2 = fmaf(p, G2[i], c2); c3 = fmaf(p, G3[i], c3);
    }
    g_coef[j] = make_float4(c0, c1, c2, c3);
    g_idx[j]  = make_int2(load_idx(ia, a64, j), load_idx(ib, b64, j));
}

// Main kernel: each block does ROWS=4 rows x all 4096 outputs.
// smem: x tile transposed as float4 per column: xs4[c] = {row0..row3}.
// Thread->j mapping is k-strided so coef/idx loads are lane-consecutive
// (fully coalesced) and stores are dense STG.32.
__global__ __launch_bounds__(THREADS, 2)
void logic_main_kernel(const float* __restrict__ x, float* __restrict__ y)
{
    extern __shared__ float xs[];   // IN_DIM * ROWS floats (64 KB)

    const int row0 = blockIdx.x * ROWS;
    const int t    = threadIdx.x;
    const int lane = t & 31;
    const int w    = t >> 5;

    // ---- stage 4 rows transposed; both LDG and STS fully coalesced ----
    // lane l: row r = l&3, colgroup cg = l>>2 ; STS addr word = base*4 + l
    {
        const int r  = lane & 3;
        const int cg = lane >> 2;
        const float* xrow = x + (size_t)(row0 + r) * IN_DIM;
        const int cbeg = w * (IN_DIM / NWARPS);        // 256 cols per warp
        #pragma unroll 4
        for (int base = cbeg; base < cbeg + (IN_DIM / NWARPS); base += 8) {
            int c = base + cg;
            xs[c * ROWS + r] = xrow[c];
        }
    }
    __syncthreads();

    const float4* __restrict__ xs4 = (const float4*)xs;

    #pragma unroll
    for (int iter = 0; iter < NITER; ++iter) {
        const int base = iter * (4 * THREADS);
        #pragma unroll
        for (int k = 0; k < 4; ++k) {
            const int j = base + k * THREADS + t;     // lane-consecutive
            const float4 cf = g_coef[j];
            const int2   ij = g_idx[j];
            const float4 a  = xs4[ij.x];
            const float4 b  = xs4[ij.y];
            const float c0 = cf.x, c1 = cf.y, c2 = cf.z, c3 = cf.w;
            // y = (c0 + c1*a) + b*(c2 + c3*a)
            float o0 = fmaf(b.x, fmaf(c3, a.x, c2), fmaf(c1, a.x, c0));
            float o1 = fmaf(b.y, fmaf(c3, a.y, c2), fmaf(c1, a.y, c0));
            float o2 = fmaf(b.z, fmaf(c3, a.z, c2), fmaf(c1, a.z, c0));
            float o3 = fmaf(b.w, fmaf(c3, a.w, c2), fmaf(c1, a.w, c0));
            y[(size_t)(row0 + 0) * OUT_DIM + j] = o0;
            y[(size_t)(row0 + 1) * OUT_DIM + j] = o1;
            y[(size_t)(row0 + 2) * OUT_DIM + j] = o2;
            y[(size_t)(row0 + 3) * OUT_DIM + j] = o3;
        }
    }
}

extern "C" void kernel_launch(void* const* d_in, const int* in_sizes, int n_in,
                              void* d_out, int out_size)
{
    const float* x  = (const float*)d_in[0];
    const float* wt = (const float*)d_in[1];
    const int*   ia = (const int*)d_in[2];
    const int*   ib = (const int*)d_in[3];
    float*       y  = (float*)d_out;

    cudaFuncSetAttribute(logic_main_kernel,
                         cudaFuncAttributeMaxDynamicSharedMemorySize,
                         IN_DIM * ROWS * (int)sizeof(float));

    precompute_kernel<<<(OUT_DIM + 255) / 256, 256>>>(wt, ia, ib);

    const int smem = IN_DIM * ROWS * (int)sizeof(float);
    logic_main_kernel<<<BATCH / ROWS, THREADS, smem>>>(x, y);
}